// round 3
// baseline (speedup 1.0000x reference)
#include <cuda_runtime.h>
#include <cstdint>

// Problem constants (fixed shapes)
#define NN   50000      // nodes
#define NE   500000     // edges (hyper-nodes after DHT)
#define NGR  64         // graphs
#define NPB  1024       // pool blocks

// ---------------- device scratch (static: no allocations allowed) ----------------
__device__ float g_bufA[(size_t)NE * 64];      // 128 MB ping
__device__ float g_bufB[(size_t)NE * 64];      // 128 MB pong
__device__ float g_agg [(size_t)NN * 64];      // per-node aggregate (L2 resident)
__device__ float g_scratch[(size_t)NPB * 4096];// pool partials
__device__ int   g_deg[NN];
__device__ int   g_cursor[NN];
__device__ float g_s[NN];
__device__ int   g_csr_off[NN + 1];
__device__ int   g_csr_edges[2 * NE];
__device__ int   g_ei0[NE];
__device__ int   g_ei1[NE];
__device__ int   g_eb[NE];
__device__ float g_imp[NE];
__device__ float g_dinv[NE];
__device__ int   g_is64;                       // 1 if index inputs are int64

// ---------------- dtype-agnostic index load ----------------
// If the harness delivers int64 data, every odd int32 word is the (zero) high
// half; if it delivers int32, words are packed. g_is64 selects the stride.
__device__ __forceinline__ int LD_IDX(const int* __restrict__ p, long long i) {
    return g_is64 ? p[2 * i] : p[(size_t)i];
}

// ---------------- f32x2 packed-math helpers (sm_103a FFMA2 path) ----------------
__device__ __forceinline__ unsigned long long fma2(unsigned long long a,
                                                   unsigned long long b,
                                                   unsigned long long c) {
    unsigned long long d;
    asm("fma.rn.f32x2 %0, %1, %2, %3;" : "=l"(d) : "l"(a), "l"(b), "l"(c));
    return d;
}
__device__ __forceinline__ unsigned long long dup2(float x) {
    unsigned long long d;
    asm("mov.b64 %0, {%1, %1};" : "=l"(d) : "f"(x));
    return d;
}
__device__ __forceinline__ float2 unpk(unsigned long long v) {
    float2 r;
    asm("mov.b64 {%0, %1}, %2;" : "=f"(r.x), "=f"(r.y) : "l"(v));
    return r;
}

// ---------------- setup kernels ----------------
__global__ void detect_kernel(const int* __restrict__ eidx) {
    if (threadIdx.x == 0 && blockIdx.x == 0) {
        int z = 0;
        #pragma unroll
        for (int i = 0; i < 64; i++) z |= eidx[2 * i + 1];
        g_is64 = (z == 0) ? 1 : 0;   // int64 non-negative values => all high words 0
    }
}

__global__ void zero_kernel() {
    int i = blockIdx.x * blockDim.x + threadIdx.x;
    if (i < NN) { g_deg[i] = 0; g_cursor[i] = 0; }
}

__global__ void deg_kernel(const int* __restrict__ eidx) {
    int e = blockIdx.x * blockDim.x + threadIdx.x;
    if (e >= NE) return;
    int a = LD_IDX(eidx, e);
    int b = LD_IDX(eidx, (long long)NE + e);
    atomicAdd(&g_deg[a], 1);
    atomicAdd(&g_deg[b], 1);
}

// single-block exclusive scan of g_deg -> g_csr_off (N=50000, 49 tiles of 1024)
__global__ void scan_kernel() {
    __shared__ int wsum[32];
    __shared__ int woff[32];
    __shared__ int s_carry, s_total;
    int tid = threadIdx.x, lane = tid & 31, wid = tid >> 5;
    if (tid == 0) s_carry = 0;
    __syncthreads();
    const int TILES = (NN + 1023) / 1024;
    for (int t = 0; t < TILES; t++) {
        int i = t * 1024 + tid;
        int v = (i < NN) ? g_deg[i] : 0;
        int incl = v;
        #pragma unroll
        for (int o = 1; o < 32; o <<= 1) {
            int u = __shfl_up_sync(0xffffffffu, incl, o);
            if (lane >= o) incl += u;
        }
        if (lane == 31) wsum[wid] = incl;
        __syncthreads();
        if (wid == 0) {
            int w = wsum[lane];
            int wi = w;
            #pragma unroll
            for (int o = 1; o < 32; o <<= 1) {
                int u = __shfl_up_sync(0xffffffffu, wi, o);
                if (lane >= o) wi += u;
            }
            woff[lane] = wi - w;
            if (lane == 31) s_total = wi;
        }
        __syncthreads();
        if (i < NN) g_csr_off[i] = s_carry + woff[wid] + (incl - v);
        __syncthreads();
        if (tid == 0) s_carry += s_total;
        __syncthreads();
    }
    if (threadIdx.x == 0) g_csr_off[NN] = s_carry;  // == 2*NE
}

__global__ void node_kernel() {
    int n = blockIdx.x * blockDim.x + threadIdx.x;
    if (n >= NN) return;
    int c = g_deg[n];
    g_s[n] = (c > 1) ? 1.0f / (float)c : 0.0f;  // deg-1 hyperedges dropped -> 0
}

__global__ void edge_kernel(const int* __restrict__ eidx,
                            const int* __restrict__ batch,
                            const float* __restrict__ nimp) {
    int e = blockIdx.x * blockDim.x + threadIdx.x;
    if (e >= NE) return;
    int a = LD_IDX(eidx, e);
    int b = LD_IDX(eidx, (long long)NE + e);
    g_ei0[e] = a;
    g_ei1[e] = b;
    g_imp[e] = fminf(nimp[a], nimp[b]);
    g_eb[e]  = LD_IDX(batch, a);
    int ka = (g_deg[a] != 1) ? 1 : 0;
    int kb = (g_deg[b] != 1) ? 1 : 0;
    g_dinv[e] = 1.0f / (float)(1 + ka + kb);   // self-loop + kept incidences
    int p = atomicAdd(&g_cursor[a], 1);
    g_csr_edges[g_csr_off[a] + p] = e;
    p = atomicAdd(&g_cursor[b], 1);
    g_csr_edges[g_csr_off[b] + p] = e;
}

// h0 = edge_attr * edge_imp (32-wide), float4 vectorized
__global__ void h0_kernel(const float* __restrict__ ea) {
    int i = blockIdx.x * blockDim.x + threadIdx.x;   // float4 index, NE*8 total
    if (i >= NE * 8) return;
    float4 v = reinterpret_cast<const float4*>(ea)[i];
    float imp = g_imp[i >> 3];
    v.x *= imp; v.y *= imp; v.z *= imp; v.w *= imp;
    reinterpret_cast<float4*>(g_bufA)[i] = v;
}

// ---------------- per-layer: node aggregation g[n] = s[n] * sum h[e] ----------------
template <int DIN, bool SRC_A>
__global__ __launch_bounds__(256) void agg_kernel() {
    const float* __restrict__ buf = SRC_A ? g_bufA : g_bufB;
    int w = blockIdx.x * 8 + (threadIdx.x >> 5);
    if (w >= NN) return;
    int lane = threadIdx.x & 31;
    float s = g_s[w];
    float a0 = 0.f, a1 = 0.f;
    if (s != 0.f) {
        int idx = g_csr_off[w], end = g_csr_off[w + 1];
        for (; idx + 2 <= end; idx += 2) {
            int e0 = g_csr_edges[idx];
            int e1 = g_csr_edges[idx + 1];
            const float* r0 = buf + (size_t)e0 * DIN;
            const float* r1 = buf + (size_t)e1 * DIN;
            float x0 = r0[lane];
            float y0 = r1[lane];
            float x1 = 0.f, y1 = 0.f;
            if (DIN == 64) { x1 = r0[lane + 32]; y1 = r1[lane + 32]; }
            a0 += x0; a0 += y0;
            if (DIN == 64) { a1 += x1; a1 += y1; }
        }
        if (idx < end) {
            const float* r0 = buf + (size_t)g_csr_edges[idx] * DIN;
            a0 += r0[lane];
            if (DIN == 64) a1 += r0[lane + 32];
        }
    }
    g_agg[(size_t)w * DIN + lane] = s * a0;
    if (DIN == 64) g_agg[(size_t)w * DIN + 32 + lane] = s * a1;
}

// ---------------- per-layer: fused stage-t + GEMM(t@W+b) + relu*imp ----------------
template <int DIN, bool SRC_A>
__global__ __launch_bounds__(256) void fused_kernel(const float* __restrict__ W,
                                                    const float* __restrict__ bias) {
    const float* __restrict__ bufIn = SRC_A ? g_bufA : g_bufB;
    float* __restrict__ bufOut      = SRC_A ? g_bufB : g_bufA;
    constexpr int PAD = 2;
    __shared__ __align__(16) float sW[DIN * 64];
    __shared__ __align__(16) float sT[64 * (DIN + PAD)];
    __shared__ float sImp[64];
    __shared__ float sB[64];
    int tid = threadIdx.x;
    int e0  = blockIdx.x * 64;

    for (int i = tid; i < DIN * 64; i += 256) sW[i] = W[i];
    if (tid < 64) sB[tid] = bias[tid];

    // stage t = Dinv * (h + g[n0] + g[n1])
    {
        int k = tid % DIN;
        for (int r = tid / DIN; r < 64; r += 256 / DIN) {
            int e = e0 + r;
            float val = 0.f;
            if (e < NE) {
                int n0 = g_ei0[e], n1 = g_ei1[e];
                float dv = g_dinv[e];
                val = dv * (bufIn[(size_t)e * DIN + k] +
                            g_agg[(size_t)n0 * DIN + k] +
                            g_agg[(size_t)n1 * DIN + k]);
                if (k == 0) sImp[r] = g_imp[e];
            } else if (k == 0) {
                sImp[r] = 0.f;
            }
            sT[r * (DIN + PAD) + k] = val;
        }
    }
    __syncthreads();

    // 64x64 tile GEMM, 4x4 microtile per thread, packed f32x2 FMA
    int ty = tid >> 4, tx = tid & 15;
    int rb = ty * 4, cb = tx * 4;
    unsigned long long acc[4][2];
    #pragma unroll
    for (int i = 0; i < 4; i++) { acc[i][0] = 0ull; acc[i][1] = 0ull; }

    #pragma unroll 8
    for (int k = 0; k < DIN; k++) {
        unsigned long long w01 = *reinterpret_cast<const unsigned long long*>(&sW[k * 64 + cb]);
        unsigned long long w23 = *reinterpret_cast<const unsigned long long*>(&sW[k * 64 + cb + 2]);
        #pragma unroll
        for (int i = 0; i < 4; i++) {
            unsigned long long t2 = dup2(sT[(rb + i) * (DIN + PAD) + k]);
            acc[i][0] = fma2(t2, w01, acc[i][0]);
            acc[i][1] = fma2(t2, w23, acc[i][1]);
        }
    }

    #pragma unroll
    for (int i = 0; i < 4; i++) {
        int e = e0 + rb + i;
        if (e < NE) {
            float imp = sImp[rb + i];
            float2 v0 = unpk(acc[i][0]);
            float2 v1 = unpk(acc[i][1]);
            float4 o;
            o.x = fmaxf(v0.x + sB[cb + 0], 0.f) * imp;
            o.y = fmaxf(v0.y + sB[cb + 1], 0.f) * imp;
            o.z = fmaxf(v1.x + sB[cb + 2], 0.f) * imp;
            o.w = fmaxf(v1.y + sB[cb + 3], 0.f) * imp;
            *reinterpret_cast<float4*>(&bufOut[(size_t)e * 64 + cb]) = o;
        }
    }
}

// ---------------- per-layer: pooled segment-sum (atomic-free) ----------------
template <bool SRC_A>
__global__ __launch_bounds__(128) void pool_kernel() {
    const float* __restrict__ buf = SRC_A ? g_bufA : g_bufB;
    __shared__ float sp[2][NGR * 64];
    int tid = threadIdx.x;
    int j = tid >> 6;          // row group 0/1
    int d = tid & 63;          // output dim; (j,d) uniquely owned by this thread
    for (int i = tid; i < 2 * NGR * 64; i += 128) (&sp[0][0])[i] = 0.f;
    __syncthreads();
    const int CHUNK = (NE + NPB - 1) / NPB;
    int base = blockIdx.x * CHUNK;
    int end  = base + CHUNK;
    if (end > NE) end = NE;
    #pragma unroll 4
    for (int r = base + j; r < end; r += 2) {
        int g = g_eb[r];
        sp[j][g * 64 + d] += buf[(size_t)r * 64 + d];
    }
    __syncthreads();
    for (int i = tid; i < NGR * 64; i += 128)
        g_scratch[(size_t)blockIdx.x * 4096 + i] = sp[0][i] + sp[1][i];
}

__global__ void reduce_kernel(float* __restrict__ out, int layer) {
    int i = blockIdx.x * blockDim.x + threadIdx.x;
    if (i >= 4096) return;
    float s = 0.f;
    for (int b = 0; b < NPB; b++) s += g_scratch[(size_t)b * 4096 + i];
    int g = i >> 6, d = i & 63;
    out[g * 192 + layer * 64 + d] = s;
}

// ---------------- launch ----------------
extern "C" void kernel_launch(void* const* d_in, const int* in_sizes, int n_in,
                              void* d_out, int out_size) {
    // inputs per metadata order: x(0) unused
    const float* edge_attr = (const float*)d_in[1];
    const int*   eidx      = (const int*)d_in[2];   // int32 or int64 (auto-detected)
    const int*   batch     = (const int*)d_in[3];
    const float* nimp      = (const float*)d_in[4];
    const float* W0 = (const float*)d_in[5];
    const float* b0 = (const float*)d_in[6];
    const float* W1 = (const float*)d_in[7];
    const float* b1 = (const float*)d_in[8];
    const float* W2 = (const float*)d_in[9];
    const float* b2 = (const float*)d_in[10];
    float* out = (float*)d_out;

    detect_kernel<<<1, 32>>>(eidx);
    zero_kernel<<<(NN + 255) / 256, 256>>>();
    deg_kernel<<<(NE + 255) / 256, 256>>>(eidx);
    scan_kernel<<<1, 1024>>>();
    node_kernel<<<(NN + 255) / 256, 256>>>();
    edge_kernel<<<(NE + 255) / 256, 256>>>(eidx, batch, nimp);
    h0_kernel<<<(NE * 8 + 255) / 256, 256>>>(edge_attr);

    const int AGG_BLKS = (NN + 7) / 8;
    const int FUS_BLKS = (NE + 63) / 64;

    // layer 1: bufA(32) -> bufB(64)
    agg_kernel<32, true><<<AGG_BLKS, 256>>>();
    fused_kernel<32, true><<<FUS_BLKS, 256>>>(W0, b0);
    pool_kernel<false><<<NPB, 128>>>();
    reduce_kernel<<<16, 256>>>(out, 0);

    // layer 2: bufB(64) -> bufA(64)
    agg_kernel<64, false><<<AGG_BLKS, 256>>>();
    fused_kernel<64, false><<<FUS_BLKS, 256>>>(W1, b1);
    pool_kernel<true><<<NPB, 128>>>();
    reduce_kernel<<<16, 256>>>(out, 1);

    // layer 3: bufA(64) -> bufB(64)
    agg_kernel<64, true><<<AGG_BLKS, 256>>>();
    fused_kernel<64, true><<<FUS_BLKS, 256>>>(W2, b2);
    pool_kernel<false><<<NPB, 128>>>();
    reduce_kernel<<<16, 256>>>(out, 2);
}

// round 5
// speedup vs baseline: 1.5323x; 1.5323x over previous
#include <cuda_runtime.h>
#include <cuda_bf16.h>
#include <cstdint>

#define NN   50000
#define NE   500000
#define NGR  64
#define FUS_BLOCKS ((NE + 127) / 128)

// ---------------- device scratch ----------------
__device__ __align__(16) __nv_bfloat16 g_hbA[(size_t)NE * 64];   // 64 MB
__device__ __align__(16) __nv_bfloat16 g_hbB[(size_t)NE * 64];   // 64 MB
__device__ __align__(16) float g_agg[(size_t)NN * 64];
__device__ int   g_deg[NN];
__device__ int   g_cursor[NN];
__device__ float g_s[NN];
__device__ int   g_csr_off[NN + 1];
__device__ int   g_bsum[64];
__device__ int   g_boff[64];
__device__ int   g_csr_edges[2 * NE];
__device__ int   g_gcnt[NGR];
__device__ int   g_gcur[NGR];
__device__ int   g_gstart[NGR + 1];
__device__ int   g_ei0p[NE];
__device__ int   g_ei1p[NE];
__device__ int   g_eorig[NE];
__device__ int   g_ebp[NE];
__device__ float g_impp[NE];
__device__ float g_dinvp[NE];
__device__ __align__(16) unsigned char g_Wb[3][2][8192];  // swizzled bf16 W (hi,lo)
__device__ int   g_is64;

// ---------------- helpers ----------------
__device__ __forceinline__ uint32_t smem_to_u32(const void* p) {
    uint32_t a;
    asm("{ .reg .u64 t; cvta.to.shared.u64 t, %1; cvt.u32.u64 %0, t; }" : "=r"(a) : "l"(p));
    return a;
}
__device__ __forceinline__ unsigned pk2(float a, float b) {
    __nv_bfloat162 t = __floats2bfloat162_rn(a, b);
    return reinterpret_cast<unsigned&>(t);
}
__device__ __forceinline__ float2 upk2(unsigned u) {
    __nv_bfloat162 t = reinterpret_cast<__nv_bfloat162&>(u);
    return __bfloat1622float2(t);
}
// XOR swizzle at 16B granularity for 128B rows: chunk ^= (row & 7)
__device__ __forceinline__ unsigned sw128(unsigned off) { return off ^ ((off >> 3) & 0x70); }

__device__ __forceinline__ int LD_IDX(const int* __restrict__ p, long long i) {
    return g_is64 ? p[2 * i] : p[(size_t)i];
}

__device__ __forceinline__ void ldsm_x4(uint32_t& a0, uint32_t& a1, uint32_t& a2, uint32_t& a3,
                                        uint32_t addr) {
    asm volatile("ldmatrix.sync.aligned.m8n8.x4.shared.b16 {%0,%1,%2,%3}, [%4];"
                 : "=r"(a0), "=r"(a1), "=r"(a2), "=r"(a3) : "r"(addr));
}
__device__ __forceinline__ void ldsm_x2(uint32_t& b0, uint32_t& b1, uint32_t addr) {
    asm volatile("ldmatrix.sync.aligned.m8n8.x2.shared.b16 {%0,%1}, [%2];"
                 : "=r"(b0), "=r"(b1) : "r"(addr));
}
__device__ __forceinline__ void mma16816(float* c, uint32_t a0, uint32_t a1, uint32_t a2,
                                         uint32_t a3, uint32_t b0, uint32_t b1) {
    asm volatile("mma.sync.aligned.m16n8k16.row.col.f32.bf16.bf16.f32 "
                 "{%0,%1,%2,%3}, {%4,%5,%6,%7}, {%8,%9}, {%0,%1,%2,%3};"
                 : "+f"(c[0]), "+f"(c[1]), "+f"(c[2]), "+f"(c[3])
                 : "r"(a0), "r"(a1), "r"(a2), "r"(a3), "r"(b0), "r"(b1));
}

// ---------------- setup ----------------
__global__ void detect_kernel(const int* __restrict__ eidx) {
    if (threadIdx.x == 0 && blockIdx.x == 0) {
        int z = 0;
        #pragma unroll
        for (int i = 0; i < 64; i++) z |= eidx[2 * i + 1];
        g_is64 = (z == 0) ? 1 : 0;
    }
}

__global__ void zero_kernel(float* __restrict__ out) {
    int i = blockIdx.x * blockDim.x + threadIdx.x;
    if (i < NN) { g_deg[i] = 0; g_cursor[i] = 0; }
    if (i < NGR) { g_gcnt[i] = 0; g_gcur[i] = 0; }
    if (i < NGR * 192) out[i] = 0.f;
}

__global__ void deg_kernel(const int* __restrict__ eidx, const int* __restrict__ batch) {
    int e = blockIdx.x * blockDim.x + threadIdx.x;
    if (e >= NE) return;
    int a = LD_IDX(eidx, e);
    int b = LD_IDX(eidx, (long long)NE + e);
    atomicAdd(&g_deg[a], 1);
    atomicAdd(&g_deg[b], 1);
    atomicAdd(&g_gcnt[LD_IDX(batch, a)], 1);
}

__global__ void scan1_kernel() {
    __shared__ int ws[32];
    __shared__ int wo[32];
    int t = threadIdx.x, lane = t & 31, w = t >> 5;
    int i = blockIdx.x * 1024 + t;
    int v = (i < NN) ? g_deg[i] : 0;
    int inc = v;
    #pragma unroll
    for (int o = 1; o < 32; o <<= 1) {
        int u = __shfl_up_sync(0xffffffffu, inc, o);
        if (lane >= o) inc += u;
    }
    if (lane == 31) ws[w] = inc;
    __syncthreads();
    if (w == 0) {
        int x = ws[lane], xi = x;
        #pragma unroll
        for (int o = 1; o < 32; o <<= 1) {
            int u = __shfl_up_sync(0xffffffffu, xi, o);
            if (lane >= o) xi += u;
        }
        wo[lane] = xi - x;
        if (lane == 31) g_bsum[blockIdx.x] = xi;
    }
    __syncthreads();
    if (i < NN) g_csr_off[i] = wo[w] + inc - v;
}

__global__ void scan2_kernel() {
    if (threadIdx.x == 0) {
        int run = 0;
        for (int b = 0; b < 49; b++) { g_boff[b] = run; run += g_bsum[b]; }
        g_csr_off[NN] = run;
        int r2 = 0;
        for (int g = 0; g < NGR; g++) { g_gstart[g] = r2; r2 += g_gcnt[g]; }
        g_gstart[NGR] = r2;
    }
}

__global__ void scan3_kernel() {
    int i = blockIdx.x * 1024 + threadIdx.x;
    if (i < NN) g_csr_off[i] += g_boff[blockIdx.x];
}

__global__ void node_kernel() {
    int n = blockIdx.x * blockDim.x + threadIdx.x;
    if (n >= NN) return;
    int c = g_deg[n];
    g_s[n] = (c > 1) ? 1.0f / (float)c : 0.0f;
}

__global__ void edge_kernel(const int* __restrict__ eidx, const int* __restrict__ batch,
                            const float* __restrict__ nimp) {
    int e = blockIdx.x * blockDim.x + threadIdx.x;
    if (e >= NE) return;
    int a = LD_IDX(eidx, e);
    int b = LD_IDX(eidx, (long long)NE + e);
    int g = LD_IDX(batch, a);
    int pe = g_gstart[g] + atomicAdd(&g_gcur[g], 1);
    g_ei0p[pe]  = a;
    g_ei1p[pe]  = b;
    g_eorig[pe] = e;
    g_ebp[pe]   = g;
    g_impp[pe]  = fminf(nimp[a], nimp[b]);
    int ka = (g_deg[a] != 1) ? 1 : 0;
    int kb = (g_deg[b] != 1) ? 1 : 0;
    g_dinvp[pe] = 1.0f / (float)(1 + ka + kb);
    int p = atomicAdd(&g_cursor[a], 1);
    g_csr_edges[g_csr_off[a] + p] = pe;
    p = atomicAdd(&g_cursor[b], 1);
    g_csr_edges[g_csr_off[b] + p] = pe;
}

// W -> split bf16 (hi, lo), [N=64][K=64] K-major rows of 128B, sw128-swizzled
__global__ void wprep_kernel(const float* __restrict__ W0, const float* __restrict__ W1,
                             const float* __restrict__ W2) {
    int l = blockIdx.x;
    const float* W = (l == 0) ? W0 : ((l == 1) ? W1 : W2);
    int KIN = (l == 0) ? 32 : 64;
    for (int i = threadIdx.x; i < 4096; i += 256) {
        int n = i >> 6, k = i & 63;
        float w = (k < KIN) ? W[k * 64 + n] : 0.f;
        __nv_bfloat16 hi = __float2bfloat16(w);
        __nv_bfloat16 lo = __float2bfloat16(w - __bfloat162float(hi));
        unsigned sw = sw128((unsigned)(n * 128 + k * 2));
        *reinterpret_cast<__nv_bfloat16*>(&g_Wb[l][0][sw]) = hi;
        *reinterpret_cast<__nv_bfloat16*>(&g_Wb[l][1][sw]) = lo;
    }
}

// ---------------- per-layer: node aggregation ----------------
__global__ __launch_bounds__(256) void agg1_kernel(const float* __restrict__ ea) {
    int n = blockIdx.x * 8 + (threadIdx.x >> 5);
    if (n >= NN) return;
    int l = threadIdx.x & 31;
    float s = g_s[n];
    float acc = 0.f;
    if (s != 0.f) {
        int i = g_csr_off[n], e = g_csr_off[n + 1];
        for (; i + 2 <= e; i += 2) {
            int p0 = g_csr_edges[i], p1 = g_csr_edges[i + 1];
            float i0 = g_impp[p0], i1 = g_impp[p1];
            acc += i0 * ea[(size_t)g_eorig[p0] * 32 + l];
            acc += i1 * ea[(size_t)g_eorig[p1] * 32 + l];
        }
        if (i < e) {
            int p = g_csr_edges[i];
            acc += g_impp[p] * ea[(size_t)g_eorig[p] * 32 + l];
        }
    }
    g_agg[(size_t)n * 32 + l] = s * acc;
}

template <bool SRCA>
__global__ __launch_bounds__(256) void agg64_kernel() {
    const __nv_bfloat16* __restrict__ hb = SRCA ? g_hbA : g_hbB;
    int n = blockIdx.x * 8 + (threadIdx.x >> 5);
    if (n >= NN) return;
    int l = threadIdx.x & 31;
    float s = g_s[n];
    float a0 = 0.f, a1 = 0.f;
    if (s != 0.f) {
        int i = g_csr_off[n], e = g_csr_off[n + 1];
        for (; i + 2 <= e; i += 2) {
            int p0 = g_csr_edges[i], p1 = g_csr_edges[i + 1];
            const __nv_bfloat162* r0 = reinterpret_cast<const __nv_bfloat162*>(hb + (size_t)p0 * 64) + l;
            const __nv_bfloat162* r1 = reinterpret_cast<const __nv_bfloat162*>(hb + (size_t)p1 * 64) + l;
            float2 f0 = __bfloat1622float2(*r0);
            float2 f1 = __bfloat1622float2(*r1);
            a0 += f0.x + f1.x;
            a1 += f0.y + f1.y;
        }
        if (i < e) {
            int p = g_csr_edges[i];
            const __nv_bfloat162* r0 = reinterpret_cast<const __nv_bfloat162*>(hb + (size_t)p * 64) + l;
            float2 f0 = __bfloat1622float2(*r0);
            a0 += f0.x; a1 += f0.y;
        }
    }
    g_agg[(size_t)n * 64 + 2 * l]     = s * a0;
    g_agg[(size_t)n * 64 + 2 * l + 1] = s * a1;
}

// ---------------- fused: stage-t(bf16,swizzled) + HMMA GEMM + epilogue ----------------
// smem: [0,16K) A/D tile (128 rows x 128B), [16K,24K) W_hi, [24K,32K) W_lo, [32K,+256) bias
#define SMEM_A_OFF  0
#define SMEM_BH_OFF 16384
#define SMEM_BS_OFF 32768
#define SMEM_TOTAL  33024

template <int LAYER>
__global__ __launch_bounds__(256) void fused_kernel(const float* __restrict__ bias,
                                                    const float* __restrict__ ea) {
    extern __shared__ char smem[];
    uint32_t sb = smem_to_u32(smem);
    int tid = threadIdx.x, wid = tid >> 5, lane = tid & 31;
    int e0 = blockIdx.x * 128;

    {   // W (hi+lo 16KB, pre-swizzled)
        const uint4* src = reinterpret_cast<const uint4*>(&g_Wb[LAYER - 1][0][0]);
        uint4* dst = reinterpret_cast<uint4*>(smem + SMEM_BH_OFF);
        #pragma unroll
        for (int i = 0; i < 4; i++) dst[tid + 256 * i] = src[tid + 256 * i];
    }
    if (tid < 64) reinterpret_cast<float*>(smem + SMEM_BS_OFF)[tid] = bias[tid];

    // ---- stage t tile (128 rows x K bf16, swizzled 128B rows) ----
    if (LAYER == 1) {
        int r = tid >> 1, hf = tid & 1;
        long long e = e0 + r;
        float v[16];
        if (e < NE) {
            int n0 = g_ei0p[e], n1 = g_ei1p[e], og = g_eorig[e];
            float dv = g_dinvp[e], im = g_impp[e];
            const float4* pa = reinterpret_cast<const float4*>(ea + (size_t)og * 32 + hf * 16);
            const float4* p0 = reinterpret_cast<const float4*>(g_agg + (size_t)n0 * 32 + hf * 16);
            const float4* p1 = reinterpret_cast<const float4*>(g_agg + (size_t)n1 * 32 + hf * 16);
            #pragma unroll
            for (int q = 0; q < 4; q++) {
                float4 a = pa[q], b = p0[q], c = p1[q];
                v[q * 4 + 0] = dv * (im * a.x + b.x + c.x);
                v[q * 4 + 1] = dv * (im * a.y + b.y + c.y);
                v[q * 4 + 2] = dv * (im * a.z + b.z + c.z);
                v[q * 4 + 3] = dv * (im * a.w + b.w + c.w);
            }
        } else {
            #pragma unroll
            for (int q = 0; q < 16; q++) v[q] = 0.f;
        }
        unsigned off = (unsigned)(r * 128 + hf * 32);
        *reinterpret_cast<uint4*>(smem + SMEM_A_OFF + sw128(off)) =
            make_uint4(pk2(v[0], v[1]), pk2(v[2], v[3]), pk2(v[4], v[5]), pk2(v[6], v[7]));
        *reinterpret_cast<uint4*>(smem + SMEM_A_OFF + sw128(off + 16)) =
            make_uint4(pk2(v[8], v[9]), pk2(v[10], v[11]), pk2(v[12], v[13]), pk2(v[14], v[15]));
    } else {
        const __nv_bfloat16* __restrict__ hin = (LAYER == 2) ? g_hbA : g_hbB;
        #pragma unroll
        for (int pass = 0; pass < 2; pass++) {
            int r = (tid >> 2) + pass * 64;
            int q = tid & 3, c0 = q * 16;
            long long e = e0 + r;
            float v[16];
            if (e < NE) {
                int n0 = g_ei0p[e], n1 = g_ei1p[e];
                float dv = g_dinvp[e];
                const uint4* ph = reinterpret_cast<const uint4*>(hin + (size_t)e * 64 + c0);
                uint4 hA = ph[0], hB = ph[1];
                float hh[16];
                float2 t2;
                t2 = upk2(hA.x); hh[0] = t2.x;  hh[1] = t2.y;
                t2 = upk2(hA.y); hh[2] = t2.x;  hh[3] = t2.y;
                t2 = upk2(hA.z); hh[4] = t2.x;  hh[5] = t2.y;
                t2 = upk2(hA.w); hh[6] = t2.x;  hh[7] = t2.y;
                t2 = upk2(hB.x); hh[8] = t2.x;  hh[9] = t2.y;
                t2 = upk2(hB.y); hh[10] = t2.x; hh[11] = t2.y;
                t2 = upk2(hB.z); hh[12] = t2.x; hh[13] = t2.y;
                t2 = upk2(hB.w); hh[14] = t2.x; hh[15] = t2.y;
                const float4* p0 = reinterpret_cast<const float4*>(g_agg + (size_t)n0 * 64 + c0);
                const float4* p1 = reinterpret_cast<const float4*>(g_agg + (size_t)n1 * 64 + c0);
                #pragma unroll
                for (int j = 0; j < 4; j++) {
                    float4 b = p0[j], c = p1[j];
                    v[j * 4 + 0] = dv * (hh[j * 4 + 0] + b.x + c.x);
                    v[j * 4 + 1] = dv * (hh[j * 4 + 1] + b.y + c.y);
                    v[j * 4 + 2] = dv * (hh[j * 4 + 2] + b.z + c.z);
                    v[j * 4 + 3] = dv * (hh[j * 4 + 3] + b.w + c.w);
                }
            } else {
                #pragma unroll
                for (int j = 0; j < 16; j++) v[j] = 0.f;
            }
            unsigned off = (unsigned)(r * 128 + c0 * 2);
            *reinterpret_cast<uint4*>(smem + SMEM_A_OFF + sw128(off)) =
                make_uint4(pk2(v[0], v[1]), pk2(v[2], v[3]), pk2(v[4], v[5]), pk2(v[6], v[7]));
            *reinterpret_cast<uint4*>(smem + SMEM_A_OFF + sw128(off + 16)) =
                make_uint4(pk2(v[8], v[9]), pk2(v[10], v[11]), pk2(v[12], v[13]), pk2(v[14], v[15]));
        }
    }
    __syncthreads();

    // ---- warp-level HMMA: each warp owns a 16-row slab, full N=64 ----
    constexpr int KSTEPS = (LAYER == 1) ? 2 : 4;
    int r0 = wid * 16;
    float acc[8][4];
    #pragma unroll
    for (int nt = 0; nt < 8; nt++) {
        acc[nt][0] = 0.f; acc[nt][1] = 0.f; acc[nt][2] = 0.f; acc[nt][3] = 0.f;
    }
    unsigned arow = (unsigned)(r0 + (lane & 15));
    unsigned abase = arow * 128 + (unsigned)(lane >> 4) * 16;
    unsigned brow = (unsigned)(lane & 7);
    unsigned bsel = (unsigned)((lane >> 3) & 1) * 16;

    #pragma unroll
    for (int kk = 0; kk < KSTEPS; kk++) {
        unsigned kb = (unsigned)kk * 32;   // k16*2 bytes
        uint32_t a0, a1, a2, a3;
        ldsm_x4(a0, a1, a2, a3, sb + SMEM_A_OFF + sw128(abase + kb));
        #pragma unroll
        for (int pass = 0; pass < 2; pass++) {
            uint32_t wb = sb + SMEM_BH_OFF + (unsigned)pass * 8192u;
            #pragma unroll
            for (int nt = 0; nt < 8; nt++) {
                uint32_t b0, b1;
                ldsm_x2(b0, b1, wb + sw128((brow + nt * 8u) * 128u + kb + bsel));
                mma16816(acc[nt], a0, a1, a2, a3, b0, b1);
            }
        }
    }

    // ---- epilogue: bias + relu + imp, bf16 into own A slab (swizzled), then copy out ----
    {
        int g = lane >> 2, q = lane & 3;
        long long ra = e0 + r0 + g, rb = ra + 8;
        float ia = (ra < NE) ? g_impp[ra] : 0.f;
        float ib = (rb < NE) ? g_impp[rb] : 0.f;
        const float* sB = reinterpret_cast<const float*>(smem + SMEM_BS_OFF);
        #pragma unroll
        for (int nt = 0; nt < 8; nt++) {
            int c0 = nt * 8 + q * 2;
            float bz0 = sB[c0], bz1 = sB[c0 + 1];
            unsigned va = pk2(fmaxf(acc[nt][0] + bz0, 0.f) * ia,
                              fmaxf(acc[nt][1] + bz1, 0.f) * ia);
            unsigned vb = pk2(fmaxf(acc[nt][2] + bz0, 0.f) * ib,
                              fmaxf(acc[nt][3] + bz1, 0.f) * ib);
            *reinterpret_cast<unsigned*>(smem + sw128((unsigned)((r0 + g) * 128 + c0 * 2))) = va;
            *reinterpret_cast<unsigned*>(smem + sw128((unsigned)((r0 + g + 8) * 128 + c0 * 2))) = vb;
        }
    }
    __syncthreads();

    {
        __nv_bfloat16* hout = (LAYER == 2) ? g_hbB : g_hbA;
        int r = tid >> 1, hf = tid & 1;
        long long e = e0 + r;
        if (e < NE) {
            uint4 x0 = *reinterpret_cast<const uint4*>(smem + sw128((unsigned)(r * 128 + hf * 64)));
            uint4 x1 = *reinterpret_cast<const uint4*>(smem + sw128((unsigned)(r * 128 + hf * 64 + 16)));
            uint4 x2 = *reinterpret_cast<const uint4*>(smem + sw128((unsigned)(r * 128 + hf * 64 + 32)));
            uint4 x3 = *reinterpret_cast<const uint4*>(smem + sw128((unsigned)(r * 128 + hf * 64 + 48)));
            uint4* dst = reinterpret_cast<uint4*>(hout + (size_t)e * 64 + hf * 32);
            dst[0] = x0; dst[1] = x1; dst[2] = x2; dst[3] = x3;
        }
    }
}

// ---------------- pool: edges sorted by group -> near-segmented sum ----------------
template <int LOFF, bool SRCA>
__global__ __launch_bounds__(256) void pool_kernel(float* __restrict__ out) {
    const __nv_bfloat16* __restrict__ hb = SRCA ? g_hbA : g_hbB;
    int j = threadIdx.x >> 6, c = threadIdx.x & 63;
    int base = blockIdx.x * 512;
    int end = base + 512;
    if (end > NE) end = NE;
    float acc = 0.f;
    int gc = -1;
    for (int r = base + j; r < end; r += 4) {
        int g = g_ebp[r];
        if (g != gc) {
            if (gc >= 0) atomicAdd(&out[gc * 192 + LOFF + c], acc);
            gc = g; acc = 0.f;
        }
        acc += __bfloat162float(hb[(size_t)r * 64 + c]);
    }
    if (gc >= 0) atomicAdd(&out[gc * 192 + LOFF + c], acc);
}

// ---------------- launch ----------------
extern "C" void kernel_launch(void* const* d_in, const int* in_sizes, int n_in,
                              void* d_out, int out_size) {
    const float* edge_attr = (const float*)d_in[1];
    const int*   eidx      = (const int*)d_in[2];
    const int*   batch     = (const int*)d_in[3];
    const float* nimp      = (const float*)d_in[4];
    const float* W0 = (const float*)d_in[5];
    const float* b0 = (const float*)d_in[6];
    const float* W1 = (const float*)d_in[7];
    const float* b1 = (const float*)d_in[8];
    const float* W2 = (const float*)d_in[9];
    const float* b2 = (const float*)d_in[10];
    float* out = (float*)d_out;

    detect_kernel<<<1, 32>>>(eidx);
    zero_kernel<<<(NN + 255) / 256, 256>>>(out);
    deg_kernel<<<(NE + 255) / 256, 256>>>(eidx, batch);
    scan1_kernel<<<49, 1024>>>();
    scan2_kernel<<<1, 32>>>();
    scan3_kernel<<<49, 1024>>>();
    node_kernel<<<(NN + 255) / 256, 256>>>();
    edge_kernel<<<(NE + 255) / 256, 256>>>(eidx, batch, nimp);
    wprep_kernel<<<3, 256>>>(W0, W1, W2);

    const int AGG_BLKS  = (NN + 7) / 8;
    const int POOL_BLKS = (NE + 511) / 512;

    // layer 1: ea -> hbA
    agg1_kernel<<<AGG_BLKS, 256>>>(edge_attr);
    fused_kernel<1><<<FUS_BLOCKS, 256, SMEM_TOTAL>>>(b0, edge_attr);
    pool_kernel<0, true><<<POOL_BLKS, 256>>>(out);

    // layer 2: hbA -> hbB
    agg64_kernel<true><<<AGG_BLKS, 256>>>();
    fused_kernel<2><<<FUS_BLOCKS, 256, SMEM_TOTAL>>>(b1, nullptr);
    pool_kernel<64, false><<<POOL_BLKS, 256>>>(out);

    // layer 3: hbB -> hbA
    agg64_kernel<false><<<AGG_BLKS, 256>>>();
    fused_kernel<3><<<FUS_BLOCKS, 256, SMEM_TOTAL>>>(b2, nullptr);
    pool_kernel<128, true><<<POOL_BLKS, 256>>>(out);
}